// round 5
// baseline (speedup 1.0000x reference)
#include <cuda_runtime.h>
#include <math.h>

// Problem constants (fixed shapes from reference)
#define Bq   4
#define Nq   2048
#define DIN  128
#define Hq   4
#define HD   32
#define Kq   204          // int(0.1 * 2048)
#define KPAD 224          // padded K (multiple of 32)
#define KSTR 228          // smem row stride (conflict-free, float4-aligned)
#define BH   (Bq*Hq)      // 16

// Scratch (device globals)
__device__ float g_Wh[BH*Nq*HD];          // [bh][n][d]  4 MB
__device__ float g_si[BH*Nq];
__device__ float g_sj[BH*Nq];
__device__ int   g_sel[BH*Kq];            // selected neighbor cols, ascending
__device__ float g_selv[BH*KPAD];         // s_j at selected (+ -3e38 pads)
__device__ float g_sjmax[BH];
__device__ float g_WhSelT[BH*HD*KPAD];    // gathered Wh, transposed [d][k]

// ---------------------------------------------------------------------------
// Kernel 1: Wh = h @ W (per head) + s_i, s_j epilogue.
// CTA: 16 rows, 256 threads. Warp w: rows (w&3)*4..+4, heads (w>>2)*2..+2.
// W staged via smem in two 64-f chunks (32 KB each).
// ---------------------------------------------------------------------------
__global__ void __launch_bounds__(256) k1_wh(const float* __restrict__ h,
                                             const float* __restrict__ W,
                                             const float* __restrict__ a)
{
    __shared__ float hs[16][DIN];     // 8 KB
    __shared__ float Ws[64][DIN];     // 32 KB  [f-local][h*32+d]
    const int tid = threadIdx.x;
    const int w   = tid >> 5;
    const int d   = tid & 31;
    const int r0  = (w & 3) * 4;
    const int h0  = (w >> 2) * 2;
    const int row0 = blockIdx.x * 16;

    ((float4*)hs)[tid]       = ((const float4*)(h + (size_t)row0 * DIN))[tid];
    ((float4*)hs)[tid + 256] = ((const float4*)(h + (size_t)row0 * DIN))[tid + 256];

    float acc[4][2];
    #pragma unroll
    for (int r = 0; r < 4; ++r) { acc[r][0] = 0.f; acc[r][1] = 0.f; }

    for (int c = 0; c < 2; ++c) {
        const int f0 = c * 64;
        __syncthreads();
        #pragma unroll
        for (int i = 0; i < 8; ++i) {
            const int lin = tid + i * 256;        // float4 index, 2048 per chunk
            const int hW  = lin >> 9;
            const int rem = lin & 511;
            const int f   = rem >> 3;
            const int dq  = rem & 7;
            *(float4*)&Ws[f][hW * 32 + dq * 4] =
                *(const float4*)(W + hW * (DIN*HD) + (f0 + f) * HD + dq * 4);
        }
        __syncthreads();

        #pragma unroll
        for (int f4 = 0; f4 < 64; f4 += 4) {
            float4 hv[4];
            #pragma unroll
            for (int r = 0; r < 4; ++r)
                hv[r] = *(const float4*)&hs[r0 + r][f0 + f4];
            #pragma unroll
            for (int u = 0; u < 4; ++u) {
                const float wv0 = Ws[f4 + u][h0 * 32 + d];
                const float wv1 = Ws[f4 + u][h0 * 32 + 32 + d];
                #pragma unroll
                for (int r = 0; r < 4; ++r) {
                    const float hvu = ((const float*)&hv[r])[u];
                    acc[r][0] += hvu * wv0;
                    acc[r][1] += hvu * wv1;
                }
            }
        }
    }

    const int b  = row0 >> 11;
    const int n0 = row0 & 2047;
    #pragma unroll
    for (int hh2 = 0; hh2 < 2; ++hh2) {
        const int hhg = h0 + hh2;
        const float ai = a[hhg * 64 + d];
        const float aj = a[hhg * 64 + 32 + d];
        const int bh = b * Hq + hhg;
        #pragma unroll
        for (int r = 0; r < 4; ++r) {
            const float val = acc[r][hh2];
            const int n = n0 + r0 + r;
            g_Wh[((size_t)bh * Nq + n) * HD + d] = val;
            float si = val * ai, sj = val * aj;
            #pragma unroll
            for (int o = 16; o; o >>= 1) {
                si += __shfl_xor_sync(0xffffffffu, si, o);
                sj += __shfl_xor_sync(0xffffffffu, sj, o);
            }
            if (d == 0) {
                g_si[bh * Nq + n] = si;
                g_sj[bh * Nq + n] = sj;
            }
        }
    }
}

// ---------------------------------------------------------------------------
// Kernel 2: per (b,h) radix-select top-K of s_j (exact jax top_k semantics).
// Gathers Wh_sel row-major (coalesced) into smem, writes transposed [d][k].
// ---------------------------------------------------------------------------
__device__ __forceinline__ int block_incscan256(int v, int* wsum)
{
    __syncthreads();
    const int lane = threadIdx.x & 31, w = threadIdx.x >> 5;
    int inc = v;
    #pragma unroll
    for (int o = 1; o < 32; o <<= 1) {
        const int t = __shfl_up_sync(0xffffffffu, inc, o);
        if (lane >= o) inc += t;
    }
    if (lane == 31) wsum[w] = inc;
    __syncthreads();
    if (threadIdx.x == 0) {
        int s = 0;
        #pragma unroll
        for (int i = 0; i < 8; ++i) { const int t = wsum[i]; wsum[i] = s; s += t; }
    }
    __syncthreads();
    return inc + wsum[w];
}

__device__ __forceinline__ int block_exscan256(int v, int* wsum)
{
    return block_incscan256(v, wsum) - v;
}

__global__ void __launch_bounds__(256) k2_select()
{
    __shared__ unsigned uvals[Nq];          // 8 KB
    __shared__ float    fvals[Nq];          // 8 KB
    __shared__ float    whT[HD * KSTR];     // 28.5 KB  [d][k]
    __shared__ int      hist[256];
    __shared__ int      wsum[8];
    __shared__ float    redf[8];
    __shared__ int      sel_s[Kq];
    __shared__ unsigned sh_pref;
    __shared__ int      sh_rem;

    const int bh  = blockIdx.x;
    const int tid = threadIdx.x;

    float mx = -3.4e38f;
    for (int j = tid; j < Nq; j += 256) {
        const float v = g_sj[bh * Nq + j];
        fvals[j] = v;
        unsigned u = __float_as_uint(v);
        u = (u & 0x80000000u) ? ~u : (u | 0x80000000u);
        uvals[j] = u;
        mx = fmaxf(mx, v);
    }
    #pragma unroll
    for (int o = 16; o; o >>= 1) mx = fmaxf(mx, __shfl_down_sync(0xffffffffu, mx, o));
    if ((tid & 31) == 0) redf[tid >> 5] = mx;
    __syncthreads();
    if (tid == 0) {
        float m = redf[0];
        #pragma unroll
        for (int i = 1; i < 8; ++i) m = fmaxf(m, redf[i]);
        g_sjmax[bh] = m;
    }

    unsigned prefix = 0;
    int remaining = Kq;
    for (int pass = 0; pass < 4; ++pass) {
        const int shift = 24 - 8 * pass;
        const unsigned mask_hi = (pass == 0) ? 0u : (0xFFFFFFFFu << (shift + 8));
        hist[tid] = 0;
        __syncthreads();
        for (int j = tid; j < Nq; j += 256) {
            const unsigned u = uvals[j];
            if ((u & mask_hi) == prefix)
                atomicAdd(&hist[(u >> shift) & 255], 1);
        }
        __syncthreads();
        const int x = hist[255 - tid];
        const int incl = block_incscan256(x, wsum);
        if (incl >= remaining && (incl - x) < remaining) {
            sh_pref = prefix | ((unsigned)(255 - tid) << shift);
            sh_rem  = remaining - (incl - x);
        }
        __syncthreads();
        prefix    = sh_pref;
        remaining = sh_rem;
        __syncthreads();
    }
    const unsigned tau = prefix;
    const int tneed    = remaining;

    const int j0 = tid * 8;
    unsigned uloc[8];
    int myeq = 0;
    #pragma unroll
    for (int e = 0; e < 8; ++e) {
        uloc[e] = uvals[j0 + e];
        if (uloc[e] == tau) myeq++;
    }
    const int eqbase = block_exscan256(myeq, wsum);

    int flags = 0, cnt = 0, eqr = eqbase;
    #pragma unroll
    for (int e = 0; e < 8; ++e) {
        bool s;
        if (uloc[e] > tau)        s = true;
        else if (uloc[e] == tau) { s = (eqr < tneed); eqr++; }
        else                      s = false;
        if (s) { flags |= (1 << e); cnt++; }
    }
    int pos = block_exscan256(cnt, wsum);
    #pragma unroll
    for (int e = 0; e < 8; ++e) {
        if (flags & (1 << e)) {
            sel_s[pos]               = j0 + e;
            g_sel [bh * Kq + pos]    = j0 + e;
            g_selv[bh * KPAD + pos]  = fvals[j0 + e];
            pos++;
        }
    }
    if (tid >= Kq && tid < KPAD) g_selv[bh * KPAD + tid] = -3.0e38f;
    __syncthreads();

    // gather row-major (coalesced LDG), store transposed into smem
    for (int idx = tid; idx < Kq * HD; idx += 256) {
        const int kk = idx >> 5, d = idx & 31;
        whT[d * KSTR + kk] = g_Wh[((size_t)bh * Nq + sel_s[kk]) * HD + d];
    }
    __syncthreads();
    // write transposed global, coalesced over k; zero pads
    for (int idx = tid; idx < HD * KPAD; idx += 256) {
        const int d = idx / KPAD, k = idx - d * KPAD;
        g_WhSelT[((size_t)bh * HD + d) * KPAD + k] = (k < Kq) ? whT[d * KSTR + k] : 0.f;
    }
}

// ---------------------------------------------------------------------------
// Fused kernel: adj routing + softmax weights + output GEMM.
// CTA = (b, 16-row tile), 512 threads, ~188 KB dynamic smem (1 CTA/SM).
//   P1 init; P2 cmap build + whs stage (4 heads); P3 route adj (coalesced
//   read, byte-map scatter to wts); P4 dense exp/z pass; P5 k-split GEMM.
// ---------------------------------------------------------------------------
#define SM_WHS   0
#define SM_WTS   116736                    // 4*32*KSTR*4
#define SM_CMAP  175104                    // + 4*16*KSTR*4
#define SM_SELV  183296                    // + 8192
#define SM_SI    186880                    // + 4*KPAD*4
#define SM_M     187136
#define SM_Z     187392
#define SM_TOT   187648

__global__ void __launch_bounds__(512) kf_main(const float* __restrict__ adj,
                                               float* __restrict__ out)
{
    extern __shared__ __align__(16) char smraw[];
    float*         whs   = (float*)(smraw + SM_WHS);    // [hh*32+d][KSTR]
    float*         wts   = (float*)(smraw + SM_WTS);    // [hh*16+r][KSTR]
    unsigned char* cmapb = (unsigned char*)(smraw + SM_CMAP);
    uint4*         cmap4 = (uint4*)cmapb;
    unsigned*      cmapw = (unsigned*)cmapb;
    float*         selv  = (float*)(smraw + SM_SELV);   // [hh*KPAD+k]
    float*         siS   = (float*)(smraw + SM_SI);     // [r*4+hh]
    float*         mS    = (float*)(smraw + SM_M);
    float*         zS    = (float*)(smraw + SM_Z);
    float*         red   = (float*)cmapb;               // reuse in P5

    const int tid  = threadIdx.x;
    const int w    = tid >> 5;
    const int lane = tid & 31;
    const int b    = blockIdx.x >> 7;
    const int tile = blockIdx.x & 127;
    const int i0   = tile * 16;
    const int bh0  = b * Hq;

    // ---- P1: init ----
    #pragma unroll
    for (int i = tid; i < Nq; i += 512) cmapw[i] = 0xFFFFFFFFu;
    for (int i = tid; i < Hq * KPAD; i += 512) {
        const int hh = i / KPAD, k = i - hh * KPAD;
        selv[hh * KPAD + k] = g_selv[(bh0 + hh) * KPAD + k];
    }
    if (tid < 64) {
        const int hh = tid & 3, r = tid >> 2;
        const float si = g_si[(bh0 + hh) * Nq + i0 + r];
        const float x  = si + g_sjmax[bh0 + hh];
        siS[r * 4 + hh] = si;
        mS[r * 4 + hh]  = (x >= 0.f) ? x : 0.2f * x;
    }
    for (int i = tid; i < 4 * 16 * (KPAD - Kq); i += 512) {   // clear k pads
        const int hh = i / (16 * (KPAD - Kq));
        const int rem = i - hh * (16 * (KPAD - Kq));
        const int r = rem / (KPAD - Kq);
        const int kk = Kq + rem - r * (KPAD - Kq);
        wts[(hh * 16 + r) * KSTR + kk] = 0.f;
    }
    __syncthreads();

    // ---- P2: cmap build + whs stage ----
    for (int i = tid; i < Hq * Kq; i += 512) {
        const int hh = i / Kq, k = i - hh * Kq;
        const int col = g_sel[(bh0 + hh) * Kq + k];
        cmapb[col * 4 + hh] = (unsigned char)k;
    }
    {
        const float4* src = (const float4*)g_WhSelT + (size_t)bh0 * HD * (KPAD / 4);
        #pragma unroll
        for (int i = tid; i < Hq * HD * (KPAD / 4); i += 512) {
            const int hh  = i / (HD * (KPAD/4));
            const int rem = i - hh * (HD * (KPAD/4));
            const int row = rem / (KPAD/4);
            const int q   = rem - row * (KPAD/4);
            *(float4*)&whs[(hh * 32 + row) * KSTR + q * 4] = src[i];
        }
    }
    __syncthreads();

    // ---- P3: routing (warp = row) ----
    {
        const float4* arow = (const float4*)(adj + (size_t)b * Nq * Nq + (size_t)(i0 + w) * Nq);
        #pragma unroll 4
        for (int it = 0; it < 16; ++it) {
            const int q = it * 32 + lane;
            const float4 av = __ldg(&arow[q]);
            const uint4  cm = cmap4[q];
            const unsigned cw[4] = {cm.x, cm.y, cm.z, cm.w};
            const float    fa[4] = {av.x, av.y, av.z, av.w};
            #pragma unroll
            for (int c = 0; c < 4; ++c) {
                const unsigned cv = cw[c];
                if (cv == 0xFFFFFFFFu) continue;
                #pragma unroll
                for (int hh = 0; hh < 4; ++hh) {
                    const unsigned kk = (cv >> (8 * hh)) & 255u;
                    if (kk != 255u) wts[(hh * 16 + w) * KSTR + kk] = fa[c];
                }
            }
        }
    }
    __syncthreads();

    // ---- P4: dense exp / z pass ----
    {
        const int gk = tid & 7;
        const int rh = tid >> 3;
        const int r  = rh & 15;
        const int hh = rh >> 4;
        const float si = siS[r * 4 + hh];
        const float m  = mS[r * 4 + hh];
        float* wrow = wts + (hh * 16 + r) * KSTR;
        const float* sv = selv + hh * KPAD;
        float zl = 0.f;
        #pragma unroll
        for (int it = 0; it < 7; ++it) {
            const int q = it * 8 + gk;
            float4 wq = *(float4*)&wrow[q * 4];
            const float4 vj = *(const float4*)&sv[q * 4];
            float x, e, p;
            x = si + vj.x; e = (x >= 0.f) ? x : 0.2f*x; p = __expf(e - m); zl += p; wq.x *= p;
            x = si + vj.y; e = (x >= 0.f) ? x : 0.2f*x; p = __expf(e - m); zl += p; wq.y *= p;
            x = si + vj.z; e = (x >= 0.f) ? x : 0.2f*x; p = __expf(e - m); zl += p; wq.z *= p;
            x = si + vj.w; e = (x >= 0.f) ? x : 0.2f*x; p = __expf(e - m); zl += p; wq.w *= p;
            *(float4*)&wrow[q * 4] = wq;
        }
        zl += __shfl_xor_sync(0xffffffffu, zl, 1);
        zl += __shfl_xor_sync(0xffffffffu, zl, 2);
        zl += __shfl_xor_sync(0xffffffffu, zl, 4);
        if (gk == 0) zS[r * 4 + hh] = zl;
    }
    __syncthreads();

    // ---- P5: GEMM, warp = (hh, row-half, k-half) ----
    {
        const int hh    = w & 3;
        const int rbase = ((w >> 2) & 1) * 8;
        const int kw    = w >> 3;
        const int kbase = kw * 112;
        const float* wh = whs + (hh * 32 + lane) * KSTR + kbase;

        float acc[8];
        #pragma unroll
        for (int r = 0; r < 8; ++r) acc[r] = 0.f;

        #pragma unroll
        for (int k0 = 0; k0 < 112; k0 += 4) {
            const float4 whv = *(const float4*)&wh[k0];
            #pragma unroll
            for (int r = 0; r < 8; ++r) {
                const float4 g = *(const float4*)&wts[(hh * 16 + rbase + r) * KSTR + kbase + k0];
                float s = acc[r];
                s += g.x * whv.x;
                s += g.y * whv.y;
                s += g.z * whv.z;
                s += g.w * whv.w;
                acc[r] = s;
            }
        }

        if (kw == 1) {
            #pragma unroll
            for (int r = 0; r < 8; ++r)
                red[(hh * 16 + rbase + r) * 32 + lane] = acc[r];
        }
        __syncthreads();
        if (kw == 0) {
            #pragma unroll
            for (int r = 0; r < 8; ++r) {
                const float tot  = acc[r] + red[(hh * 16 + rbase + r) * 32 + lane];
                const float invz = 1.0f / zS[(rbase + r) * 4 + hh];
                out[((size_t)(b * Nq + i0 + rbase + r)) * (Hq * HD) + hh * HD + lane] = tot * invz;
            }
        }
    }
}

// ---------------------------------------------------------------------------
extern "C" void kernel_launch(void* const* d_in, const int* in_sizes, int n_in,
                              void* d_out, int out_size)
{
    const float *h = nullptr, *adj = nullptr, *W = nullptr, *a = nullptr;
    for (int i = 0; i < n_in; ++i) {
        switch (in_sizes[i]) {
            case Bq*Nq*DIN:  h   = (const float*)d_in[i]; break;  // 1048576
            case Bq*Nq*Nq:   adj = (const float*)d_in[i]; break;  // 16777216
            case Hq*DIN*HD:  W   = (const float*)d_in[i]; break;  // 16384
            case Hq*2*HD:    a   = (const float*)d_in[i]; break;  // 256
            default: break;
        }
    }
    float* out = (float*)d_out;

    cudaFuncSetAttribute(kf_main, cudaFuncAttributeMaxDynamicSharedMemorySize, SM_TOT);

    k1_wh    <<<(Bq*Nq)/16, 256>>>(h, W, a);
    k2_select<<<BH, 256>>>();
    kf_main  <<<Bq * (Nq/16), 512, SM_TOT>>>(adj, out);
}